// round 4
// baseline (speedup 1.0000x reference)
#include <cuda_runtime.h>
#include <cstdint>

#define N_NODES 100000
#define N_EDGES 3200000
#define SCAN_BLK 1024
#define NSCAN ((N_NODES + SCAN_BLK - 1) / SCAN_BLK)   // 98

// ---------------------------------------------------------------------------
// Scratch (__device__ globals; no allocations allowed)
// ---------------------------------------------------------------------------
__device__ float g_xr1[N_NODES * 32];
__device__ float g_acc1[N_NODES * 32];
__device__ float g_xr2[N_NODES * 32];
__device__ float g_acc2[N_NODES * 32];
__device__ float g_xr3[N_NODES * 8];
__device__ float g_wt1[128 * 64];
__device__ float g_wt2[32 * 64];
__device__ float g_wt3[32 * 16];
// CSR build
__device__ int   g_cnt[N_NODES];
__device__ int   g_row_start[N_NODES + 1];
__device__ int   g_cursor[N_NODES];
__device__ int   g_blk[SCAN_BLK];        // block sums (NSCAN used)
__device__ int   g_blkoff[SCAN_BLK];
__device__ uint2 g_perm[N_EDGES];        // {src, weight_bits} sorted by dst

// ---------------------------------------------------------------------------
// Weight transpose into k-major concat panels wt[k][o] (o<H: rel, o>=H: root)
// Also zeroes g_cnt (runs before hist_kernel in stream order).
// ---------------------------------------------------------------------------
__global__ void transpose_weights_kernel(
    const float* __restrict__ w1r, const float* __restrict__ w1o,
    const float* __restrict__ w2r, const float* __restrict__ w2o,
    const float* __restrict__ w3r, const float* __restrict__ w3o)
{
    int tid = blockIdx.x * blockDim.x + threadIdx.x;
    int stride = gridDim.x * blockDim.x;
    for (int i = tid; i < N_NODES; i += stride) g_cnt[i] = 0;
    for (int i = tid; i < 128 * 64; i += stride) {
        int k = i >> 6, o = i & 63;
        g_wt1[i] = (o < 32) ? w1r[o * 128 + k] : w1o[(o - 32) * 128 + k];
    }
    for (int i = tid; i < 32 * 64; i += stride) {
        int k = i >> 6, o = i & 63;
        g_wt2[i] = (o < 32) ? w2r[o * 32 + k] : w2o[(o - 32) * 32 + k];
    }
    for (int i = tid; i < 32 * 16; i += stride) {
        int k = i >> 4, o = i & 15;
        g_wt3[i] = (o < 8) ? w3r[o * 32 + k] : w3o[(o - 8) * 32 + k];
    }
}

// ---------------------------------------------------------------------------
// CSR build: histogram -> 2-level exclusive scan -> permute
// ---------------------------------------------------------------------------
__global__ void hist_kernel(const int* __restrict__ ei)
{
    int e = blockIdx.x * 256 + threadIdx.x;
    if (e < N_EDGES) atomicAdd(&g_cnt[ei[N_EDGES + e]], 1);
}

__global__ void scan1_kernel()
{
    __shared__ int s[SCAN_BLK];
    int tid = threadIdx.x;
    int i = blockIdx.x * SCAN_BLK + tid;
    int c = (i < N_NODES) ? g_cnt[i] : 0;
    s[tid] = c; __syncthreads();
    for (int off = 1; off < SCAN_BLK; off <<= 1) {
        int v = (tid >= off) ? s[tid - off] : 0;
        __syncthreads();
        s[tid] += v; __syncthreads();
    }
    if (i < N_NODES) g_row_start[i] = s[tid] - c;   // exclusive
    if (tid == SCAN_BLK - 1) g_blk[blockIdx.x] = s[tid];
}

__global__ void scan2_kernel()
{
    __shared__ int s[128];
    int tid = threadIdx.x;
    int c = (tid < NSCAN) ? g_blk[tid] : 0;
    s[tid] = c; __syncthreads();
    for (int off = 1; off < 128; off <<= 1) {
        int v = (tid >= off) ? s[tid - off] : 0;
        __syncthreads();
        s[tid] += v; __syncthreads();
    }
    if (tid < NSCAN) g_blkoff[tid] = s[tid] - c;    // exclusive
}

__global__ void scan3_kernel()
{
    int i = blockIdx.x * SCAN_BLK + threadIdx.x;
    if (i < N_NODES) {
        int v = g_row_start[i] + g_blkoff[i >> 10];
        g_row_start[i] = v;
        g_cursor[i] = v;
    }
    if (i == 0) g_row_start[N_NODES] = N_EDGES;
}

__global__ void permute_kernel(const int* __restrict__ ei,
                               const float* __restrict__ ew)
{
    int e = blockIdx.x * 256 + threadIdx.x;
    if (e >= N_EDGES) return;
    int src = ei[e];
    int dst = ei[N_EDGES + e];
    float w = ew[e];
    int pos = atomicAdd(&g_cursor[dst], 1);
    g_perm[pos] = make_uint2((unsigned)src, __float_as_uint(w));
}

// ---------------------------------------------------------------------------
// Fused node GEMM:
//   xr[n][0:H]  = act(X[n]) @ W_rel^T
//   acc[n][0:H] = act(X[n]) @ W_root^T + bias
// As stored node-major [BM][BK]: inner-loop a-reads are warp broadcasts
// (conflict-free, no padding), tile stores bank-spread.
// ---------------------------------------------------------------------------
template<int K, int HOUT, int BM, int TM, bool LRELU>
__global__ __launch_bounds__(256)
void gemm_kernel(const float* __restrict__ X, const float* __restrict__ Wt,
                 const float* __restrict__ bias,
                 float* __restrict__ xr, float* __restrict__ acc)
{
    constexpr int BN = 2 * HOUT;        // 64 or 16
    constexpr int TN = BN / 16;         // 4 or 1
    constexpr int BK = 32;
    static_assert(BM == TM * 16, "block shape");

    __shared__ float As[BM][BK];
    __shared__ float Ws[K][BN];

    const int tid = threadIdx.x;
    const int tx = tid & 15;
    const int ty = tid >> 4;
    const int m_blk = blockIdx.x * BM;

    for (int i = tid * 4; i < K * BN; i += 256 * 4)
        *(float4*)&Ws[0][i] = *(const float4*)&Wt[i];

    float r[TM][TN];
#pragma unroll
    for (int j = 0; j < TM; j++)
#pragma unroll
        for (int n = 0; n < TN; n++) r[j][n] = 0.f;

    for (int k0 = 0; k0 < K; k0 += BK) {
        __syncthreads();
#pragma unroll
        for (int i = tid; i < BM * BK; i += 256) {
            int m = i >> 5, kk = i & 31;
            int node = m_blk + m;
            float v = 0.f;
            if (node < N_NODES) {
                v = X[(size_t)node * K + k0 + kk];
                if (LRELU) v = (v > 0.f) ? v : 0.01f * v;
            }
            As[m][kk] = v;
        }
        __syncthreads();

#pragma unroll
        for (int kk = 0; kk < BK; kk++) {
            float a[TM];
#pragma unroll
            for (int j = 0; j < TM; j++) a[j] = As[ty * TM + j][kk];
            float b[TN];
            if (TN == 4) {
                float4 bv = *(const float4*)&Ws[k0 + kk][tx * 4];
                b[0] = bv.x; b[1 % TN] = bv.y; b[2 % TN] = bv.z; b[3 % TN] = bv.w;
            } else {
                b[0] = Ws[k0 + kk][tx];
            }
#pragma unroll
            for (int j = 0; j < TM; j++)
#pragma unroll
                for (int n = 0; n < TN; n++)
                    r[j][n] += a[j] * b[n];
        }
    }

#pragma unroll
    for (int j = 0; j < TM; j++) {
        int node = m_blk + ty * TM + j;
        if (node >= N_NODES) continue;
        if (TN == 4) {
            if (tx < 8) {
                float4 v = make_float4(r[j][0], r[j][1 % TN], r[j][2 % TN], r[j][3 % TN]);
                *(float4*)&xr[(size_t)node * HOUT + tx * 4] = v;
            } else {
                int o = (tx - 8) * 4;
                float4 v = make_float4(r[j][0] + bias[o + 0],
                                       r[j][1 % TN] + bias[o + 1],
                                       r[j][2 % TN] + bias[o + 2],
                                       r[j][3 % TN] + bias[o + 3]);
                *(float4*)&acc[(size_t)node * HOUT + o] = v;
            }
        } else {
            if (tx < HOUT) {
                xr[(size_t)node * HOUT + tx] = r[j][0];
            } else {
                acc[(size_t)node * HOUT + (tx - HOUT)] = r[j][0] + bias[tx - HOUT];
            }
        }
    }
}

// ---------------------------------------------------------------------------
// CSR gather: one warp per dst node, lane = feature (lane < D active).
// All 32 lanes cooperatively stage up to 32 edge metas, then shfl-broadcast.
// acc[d] += sum_e w_e * xr[src_e]  — no atomics, single write per node.
// ---------------------------------------------------------------------------
template<int D>
__global__ __launch_bounds__(256)
void gather_kernel(const float* __restrict__ xr, float* __restrict__ acc)
{
    int w = (blockIdx.x * 256 + threadIdx.x) >> 5;   // warp-uniform
    int lane = threadIdx.x & 31;
    if (w >= N_NODES) return;

    int s = g_row_start[w];
    int e = g_row_start[w + 1];
    float sum = 0.f;

    for (int base = s; base < e; base += 32) {
        int n = e - base; if (n > 32) n = 32;
        uint2 meta = make_uint2(0u, 0u);
        if (base + lane < e) meta = g_perm[base + lane];
#pragma unroll 4
        for (int j = 0; j < n; j++) {
            int   src = (int)__shfl_sync(0xffffffffu, meta.x, j);
            float wt  = __uint_as_float(__shfl_sync(0xffffffffu, meta.y, j));
            float v = 0.f;
            if (D == 32 || lane < D) v = __ldg(&xr[(size_t)src * D + lane]);
            sum += wt * v;
        }
    }
    if (D == 32 || lane < D)
        acc[(size_t)w * D + lane] += sum;
}

// ---------------------------------------------------------------------------
// Launch
// ---------------------------------------------------------------------------
extern "C" void kernel_launch(void* const* d_in, const int* in_sizes, int n_in,
                              void* d_out, int out_size)
{
    const float* x      = (const float*)d_in[0];
    const int*   ei     = (const int*)d_in[1];
    const float* ew     = (const float*)d_in[2];
    const float* W1_rel = (const float*)d_in[3];
    const float* b1     = (const float*)d_in[4];
    const float* W1_root= (const float*)d_in[5];
    const float* W2_rel = (const float*)d_in[6];
    const float* b2     = (const float*)d_in[7];
    const float* W2_root= (const float*)d_in[8];
    const float* W3_rel = (const float*)d_in[9];
    const float* b3     = (const float*)d_in[10];
    const float* W3_root= (const float*)d_in[11];
    float* out = (float*)d_out;

    float *xr1, *acc1, *xr2, *acc2, *xr3, *wt1, *wt2, *wt3;
    cudaGetSymbolAddress((void**)&xr1,  g_xr1);
    cudaGetSymbolAddress((void**)&acc1, g_acc1);
    cudaGetSymbolAddress((void**)&xr2,  g_xr2);
    cudaGetSymbolAddress((void**)&acc2, g_acc2);
    cudaGetSymbolAddress((void**)&xr3,  g_xr3);
    cudaGetSymbolAddress((void**)&wt1,  g_wt1);
    cudaGetSymbolAddress((void**)&wt2,  g_wt2);
    cudaGetSymbolAddress((void**)&wt3,  g_wt3);

    const int edge_blocks   = (N_EDGES + 255) / 256;       // 12500
    const int gather_blocks = (N_NODES + 7) / 8;           // warp per node, 8/blk
    const int g1_blocks     = (N_NODES + 127) / 128;
    const int g2_blocks     = (N_NODES + 63) / 64;

    // --- CSR build (also zeroes g_cnt inside transpose kernel) ---
    transpose_weights_kernel<<<32, 256>>>(W1_rel, W1_root, W2_rel, W2_root,
                                          W3_rel, W3_root);
    hist_kernel<<<edge_blocks, 256>>>(ei);
    scan1_kernel<<<NSCAN, SCAN_BLK>>>();
    scan2_kernel<<<1, 128>>>();
    scan3_kernel<<<NSCAN, SCAN_BLK>>>();
    permute_kernel<<<edge_blocks, 256>>>(ei, ew);

    // --- Layer 1: project 128->32 first, then gather ---
    gemm_kernel<128, 32, 128, 8, false><<<g1_blocks, 256>>>(x, wt1, b1, xr1, acc1);
    gather_kernel<32><<<gather_blocks, 256>>>(xr1, acc1);

    // --- Layer 2 (leaky-relu fused on load) ---
    gemm_kernel<32, 32, 64, 4, true><<<g2_blocks, 256>>>(acc1, wt2, b2, xr2, acc2);
    gather_kernel<32><<<gather_blocks, 256>>>(xr2, acc2);

    // --- Layer 3 -> d_out ---
    gemm_kernel<32, 8, 64, 4, true><<<g2_blocks, 256>>>(acc2, wt3, b3, xr3, out);
    gather_kernel<8><<<gather_blocks, 256>>>(xr3, out);
}

// round 10
// speedup vs baseline: 1.1563x; 1.1563x over previous
#include <cuda_runtime.h>
#include <cstdint>

#define N_NODES 100000
#define N_EDGES 3200000

// ---------------------------------------------------------------------------
// Scratch (no allocations allowed -> __device__ globals)
// ---------------------------------------------------------------------------
__device__ float g_xr1[N_NODES * 32];   // x @ W1_rel^T
__device__ float g_acc1[N_NODES * 32];  // x @ W1_root^T + b1, then += scatter
__device__ float g_xr2[N_NODES * 32];
__device__ float g_acc2[N_NODES * 32];
__device__ float g_xr3[N_NODES * 8];
__device__ float g_wt1[128 * 64];       // k-major concat(W1_rel, W1_root)
__device__ float g_wt2[32 * 64];
__device__ float g_wt3[32 * 16];

// ---------------------------------------------------------------------------
// Transpose weights into k-major concatenated panels: wt[k][o],
// o in [0, HOUT) = rel rows, o in [HOUT, 2*HOUT) = root rows.
// ---------------------------------------------------------------------------
__global__ void transpose_weights_kernel(
    const float* __restrict__ w1r, const float* __restrict__ w1o,
    const float* __restrict__ w2r, const float* __restrict__ w2o,
    const float* __restrict__ w3r, const float* __restrict__ w3o)
{
    int tid = blockIdx.x * blockDim.x + threadIdx.x;
    int stride = gridDim.x * blockDim.x;
    for (int i = tid; i < 128 * 64; i += stride) {
        int k = i >> 6, o = i & 63;
        g_wt1[i] = (o < 32) ? w1r[o * 128 + k] : w1o[(o - 32) * 128 + k];
    }
    for (int i = tid; i < 32 * 64; i += stride) {
        int k = i >> 6, o = i & 63;
        g_wt2[i] = (o < 32) ? w2r[o * 32 + k] : w2o[(o - 32) * 32 + k];
    }
    for (int i = tid; i < 32 * 16; i += stride) {
        int k = i >> 4, o = i & 15;
        g_wt3[i] = (o < 8) ? w3r[o * 32 + k] : w3o[(o - 8) * 32 + k];
    }
}

// ---------------------------------------------------------------------------
// Fused node GEMM:
//   xr[n][0:H]  = act(X[n]) @ W_rel^T
//   acc[n][0:H] = act(X[n]) @ W_root^T + bias
// As k-major [BK][BM+4]: +4 pad keeps float4 alignment (row stride % 4 == 0)
// while spreading store banks; a-operand fetched as LDS.128 (2 distinct
// addresses per warp -> conflict-free), b-operand LDS.128 from Ws.
// Inner loop per kk: 2-3 LDS.128 + TM*TN FMA  (~89% FMA mix).
// ---------------------------------------------------------------------------
template<int K, int HOUT, int BM, int TM, int BK, bool LRELU>
__global__ __launch_bounds__(256)
void gemm_kernel(const float* __restrict__ X, const float* __restrict__ Wt,
                 const float* __restrict__ bias,
                 float* __restrict__ xr, float* __restrict__ acc)
{
    constexpr int BN = 2 * HOUT;        // 64 or 16
    constexpr int TN = BN / 16;         // 4 or 1
    static_assert(BM == TM * 16, "block shape");
    static_assert((BM + 4) % 4 == 0 && TM % 4 == 0, "float4 alignment");

    __shared__ float As[BK][BM + 4];
    __shared__ float Ws[K][BN];

    const int tid = threadIdx.x;
    const int tx = tid & 15;
    const int ty = tid >> 4;
    const int m_blk = blockIdx.x * BM;

    // Full k-major weight panel resident in smem (coalesced float4)
    for (int i = tid * 4; i < K * BN; i += 256 * 4)
        *(float4*)&Ws[0][i] = *(const float4*)&Wt[i];

    float r[TM][TN];
#pragma unroll
    for (int j = 0; j < TM; j++)
#pragma unroll
        for (int n = 0; n < TN; n++) r[j][n] = 0.f;

    for (int k0 = 0; k0 < K; k0 += BK) {
        __syncthreads();
        // Load A tile transposed: coalesced global read along k, store As[kk][m]
#pragma unroll
        for (int i = tid; i < BM * BK; i += 256) {
            int m = i / BK, kk = i % BK;
            int node = m_blk + m;
            float v = 0.f;
            if (node < N_NODES) {
                v = X[(size_t)node * K + k0 + kk];
                if (LRELU) v = (v > 0.f) ? v : 0.01f * v;
            }
            As[kk][m] = v;
        }
        __syncthreads();

#pragma unroll
        for (int kk = 0; kk < BK; kk++) {
            float a[TM];
#pragma unroll
            for (int j4 = 0; j4 < TM; j4 += 4) {
                float4 av = *(const float4*)&As[kk][ty * TM + j4];
                a[j4 + 0] = av.x; a[j4 + 1] = av.y;
                a[j4 + 2] = av.z; a[j4 + 3] = av.w;
            }
            float b[TN];
            if (TN == 4) {
                float4 bv = *(const float4*)&Ws[k0 + kk][tx * 4];
                b[0] = bv.x; b[1 % TN] = bv.y; b[2 % TN] = bv.z; b[3 % TN] = bv.w;
            } else {
                b[0] = Ws[k0 + kk][tx];
            }
#pragma unroll
            for (int j = 0; j < TM; j++)
#pragma unroll
                for (int n = 0; n < TN; n++)
                    r[j][n] += a[j] * b[n];
        }
    }

    // Epilogue: tx*TN in [0,HOUT) -> xr ; [HOUT,2*HOUT) -> acc (+bias)
#pragma unroll
    for (int j = 0; j < TM; j++) {
        int node = m_blk + ty * TM + j;
        if (node >= N_NODES) continue;
        if (TN == 4) {
            if (tx < 8) {
                float4 v = make_float4(r[j][0], r[j][1 % TN], r[j][2 % TN], r[j][3 % TN]);
                *(float4*)&xr[(size_t)node * HOUT + tx * 4] = v;
            } else {
                int o = (tx - 8) * 4;
                float4 v = make_float4(r[j][0] + bias[o + 0],
                                       r[j][1 % TN] + bias[o + 1],
                                       r[j][2 % TN] + bias[o + 2],
                                       r[j][3 % TN] + bias[o + 3]);
                *(float4*)&acc[(size_t)node * HOUT + o] = v;
            }
        } else {
            if (tx < HOUT) {
                xr[(size_t)node * HOUT + tx] = r[j][0];
            } else {
                acc[(size_t)node * HOUT + (tx - HOUT)] = r[j][0] + bias[tx - HOUT];
            }
        }
    }
}

// ---------------------------------------------------------------------------
// Edge scatter: acc[dst] += ew * xr[src], one float4 chunk per thread,
// vector L2 reduction (red.global.add.v4.f32). Edge meta streamed (.cs).
// This kernel is at the L2 roofline (~820 MB per 32-dim layer).
// ---------------------------------------------------------------------------
template<int D>
__global__ __launch_bounds__(256)
void scatter_kernel(const int* __restrict__ ei, const float* __restrict__ ew,
                    const float* __restrict__ xr, float* __restrict__ acc)
{
    constexpr int CPE = D / 4;                 // chunks per edge (8 or 2)
    const int total = N_EDGES * CPE;
    int gid = blockIdx.x * 256 + threadIdx.x;
    if (gid >= total) return;

    const int e = gid / CPE;
    const int c = gid - e * CPE;

    const int src = __ldcs(&ei[e]);
    const int dst = __ldcs(&ei[N_EDGES + e]);
    const float w = __ldcs(&ew[e]);

    float4 v = *(const float4*)(xr + (size_t)src * D + c * 4);
    v.x *= w; v.y *= w; v.z *= w; v.w *= w;

    float* p = acc + (size_t)dst * D + c * 4;
    asm volatile("red.global.add.v4.f32 [%0], {%1, %2, %3, %4};"
                 :: "l"(p), "f"(v.x), "f"(v.y), "f"(v.z), "f"(v.w)
                 : "memory");
}

// ---------------------------------------------------------------------------
// Launch
// ---------------------------------------------------------------------------
extern "C" void kernel_launch(void* const* d_in, const int* in_sizes, int n_in,
                              void* d_out, int out_size)
{
    const float* x      = (const float*)d_in[0];
    const int*   ei     = (const int*)d_in[1];
    const float* ew     = (const float*)d_in[2];
    const float* W1_rel = (const float*)d_in[3];
    const float* b1     = (const float*)d_in[4];
    const float* W1_root= (const float*)d_in[5];
    const float* W2_rel = (const float*)d_in[6];
    const float* b2     = (const float*)d_in[7];
    const float* W2_root= (const float*)d_in[8];
    const float* W3_rel = (const float*)d_in[9];
    const float* b3     = (const float*)d_in[10];
    const float* W3_root= (const float*)d_in[11];
    float* out = (float*)d_out;

    float *xr1, *acc1, *xr2, *acc2, *xr3, *wt1, *wt2, *wt3;
    cudaGetSymbolAddress((void**)&xr1,  g_xr1);
    cudaGetSymbolAddress((void**)&acc1, g_acc1);
    cudaGetSymbolAddress((void**)&xr2,  g_xr2);
    cudaGetSymbolAddress((void**)&acc2, g_acc2);
    cudaGetSymbolAddress((void**)&xr3,  g_xr3);
    cudaGetSymbolAddress((void**)&wt1,  g_wt1);
    cudaGetSymbolAddress((void**)&wt2,  g_wt2);
    cudaGetSymbolAddress((void**)&wt3,  g_wt3);

    const int g1_blocks   = (N_NODES + 127) / 128;   // BM=128
    const int g2_blocks   = (N_NODES + 63) / 64;     // BM=64
    const int sc32_blocks = (N_EDGES * 8 + 255) / 256;
    const int sc8_blocks  = (N_EDGES * 2 + 255) / 256;

    transpose_weights_kernel<<<16, 256>>>(W1_rel, W1_root, W2_rel, W2_root,
                                          W3_rel, W3_root);

    // Layer 1: project 128->32 first (commute W_rel with segment_sum)
    gemm_kernel<128, 32, 128, 8, 16, false><<<g1_blocks, 256>>>(x, wt1, b1, xr1, acc1);
    scatter_kernel<32><<<sc32_blocks, 256>>>(ei, ew, xr1, acc1);

    // Layer 2 (leaky-relu fused on load)
    gemm_kernel<32, 32, 64, 4, 32, true><<<g2_blocks, 256>>>(acc1, wt2, b2, xr2, acc2);
    scatter_kernel<32><<<sc32_blocks, 256>>>(ei, ew, xr2, acc2);

    // Layer 3 -> d_out
    gemm_kernel<32, 8, 64, 4, 32, true><<<g2_blocks, 256>>>(acc2, wt3, b3, xr3, out);
    scatter_kernel<8><<<sc8_blocks, 256>>>(ei, ew, xr3, out);
}